// round 4
// baseline (speedup 1.0000x reference)
#include <cuda_runtime.h>
#include <cstdint>

// Problem constants
#define B   8
#define T   2048
#define C   256
#define L   32
#define DQ  512
#define WSZ 32
#define NCH 8
#define CIC 4
#define NW  2017      // T - WSZ + 1
#define NS  2045      // T - CIC + 1 (distinct 4-window starts)
#define DSPLIT 16     // d-split for enc partial GEMM

// ---------------- scratch (device globals; no allocs allowed) ----------------
__device__ float g_part1[DSPLIT * B * L * C];   // 4 MB
__device__ float g_part2[DSPLIT * B * L * C];   // 4 MB
__device__ float g_enc1[B * L * C];             // 256 KB
__device__ float g_enc2[B * L * C];             // 256 KB
__device__ int   g_labels[B * T];               // 64 KB
__device__ float g_mean4[(size_t)B * NS * C];   // 16.75 MB
__device__ int   g_maj4[B * NS];                // 65 KB

// ---------------------------------------------------------------------------
// K1a: partial enc GEMMs.  enc{1,2}[b,l,c] = sum_d query[b,l,d]*W{1,2}[d,c]
// grid (DSPLIT, B), 256 threads. Each block: full 32x256 tile over a 32-wide
// d-chunk. Warp = 4 l's (register-blocked), lanes cover c via 2x float4.
// ---------------------------------------------------------------------------
__global__ void k_enc_partial(const float* __restrict__ query,
                              const float* __restrict__ W1,
                              const float* __restrict__ W2) {
    __shared__ float q_s[L * 32];   // [l][dd]
    const int b  = blockIdx.y;
    const int dc = blockIdx.x;
    const int d0 = dc * 32;

    for (int i = threadIdx.x; i < L * 32; i += 256) {
        int l = i >> 5, dd = i & 31;
        q_s[i] = query[((b * L + l) * DQ) + d0 + dd];
    }
    __syncthreads();

    const int warp = threadIdx.x >> 5, lane = threadIdx.x & 31;

    float4 a1[4][2], a2[4][2];
#pragma unroll
    for (int i = 0; i < 4; i++)
#pragma unroll
        for (int p = 0; p < 2; p++) {
            a1[i][p] = make_float4(0.f, 0.f, 0.f, 0.f);
            a2[i][p] = make_float4(0.f, 0.f, 0.f, 0.f);
        }

    for (int dd = 0; dd < 32; dd++) {
        const int d = d0 + dd;
        const float4* w1r = (const float4*)(W1 + d * C);
        const float4* w2r = (const float4*)(W2 + d * C);
        float4 w1a = w1r[lane], w1b = w1r[lane + 32];
        float4 w2a = w2r[lane], w2b = w2r[lane + 32];
#pragma unroll
        for (int i = 0; i < 4; i++) {
            float q = q_s[(warp * 4 + i) * 32 + dd];
            a1[i][0].x += q * w1a.x; a1[i][0].y += q * w1a.y;
            a1[i][0].z += q * w1a.z; a1[i][0].w += q * w1a.w;
            a1[i][1].x += q * w1b.x; a1[i][1].y += q * w1b.y;
            a1[i][1].z += q * w1b.z; a1[i][1].w += q * w1b.w;
            a2[i][0].x += q * w2a.x; a2[i][0].y += q * w2a.y;
            a2[i][0].z += q * w2a.z; a2[i][0].w += q * w2a.w;
            a2[i][1].x += q * w2b.x; a2[i][1].y += q * w2b.y;
            a2[i][1].z += q * w2b.z; a2[i][1].w += q * w2b.w;
        }
    }

#pragma unroll
    for (int i = 0; i < 4; i++) {
        int l = warp * 4 + i;
        float4* p1 = (float4*)(g_part1 + (((size_t)dc * B + b) * L + l) * C);
        float4* p2 = (float4*)(g_part2 + (((size_t)dc * B + b) * L + l) * C);
        p1[lane] = a1[i][0]; p1[lane + 32] = a1[i][1];
        p2[lane] = a2[i][0]; p2[lane + 32] = a2[i][1];
    }
}

// K1b: reduce d-split partials + bias. grid (B*L), 256 threads (thread = c).
__global__ void k_enc_reduce(const float* __restrict__ b1,
                             const float* __restrict__ b2) {
    const int b = blockIdx.x >> 5, l = blockIdx.x & 31, c = threadIdx.x;
    float s1 = 0.f, s2 = 0.f;
#pragma unroll
    for (int dc = 0; dc < DSPLIT; dc++) {
        size_t idx = (((size_t)dc * B + b) * L + l) * C + c;
        s1 += g_part1[idx];
        s2 += g_part2[idx];
    }
    g_enc1[(b * L + l) * C + c] = s1 + b1[c];
    g_enc2[(b * L + l) * C + c] = s2 + b2[c];
}

// ---------------------------------------------------------------------------
// K2: clip_labels[b,t] = argmax_l sum_c vis[b,t,c]*enc1[b,l,c]
// grid (T/32, B), 256 threads. enc1[b] staged in smem; each warp holds 4 vis
// rows in registers (4x reuse of enc1 smem reads), butterfly-reduces 4 sims
// per l, tracks first-occurrence argmax (strict >, ascending l).
// ---------------------------------------------------------------------------
__global__ void k_labels(const float* __restrict__ vis) {
    __shared__ float e_s[L * C];   // 32 KB
    const int b = blockIdx.y, t0 = blockIdx.x * 32;

    for (int i = threadIdx.x; i < L * C; i += 256)
        e_s[i] = g_enc1[b * L * C + i];
    __syncthreads();

    const int warp = threadIdx.x >> 5, lane = threadIdx.x & 31;
    const int tb = t0 + warp * 4;

    float v[4][8];
#pragma unroll
    for (int i = 0; i < 4; i++) {
        const float* vr = vis + ((size_t)(b * T + tb + i)) * C;
#pragma unroll
        for (int j = 0; j < 8; j++) v[i][j] = vr[lane + 32 * j];
    }

    float best[4]; int bl[4];
#pragma unroll
    for (int i = 0; i < 4; i++) { best[i] = -3.4e38f; bl[i] = 0; }

    for (int l = 0; l < L; l++) {
        float s0 = 0.f, s1 = 0.f, s2 = 0.f, s3 = 0.f;
#pragma unroll
        for (int j = 0; j < 8; j++) {
            float e = e_s[l * C + lane + 32 * j];
            s0 += v[0][j] * e;
            s1 += v[1][j] * e;
            s2 += v[2][j] * e;
            s3 += v[3][j] * e;
        }
#pragma unroll
        for (int o = 16; o; o >>= 1) {
            s0 += __shfl_xor_sync(0xffffffffu, s0, o);
            s1 += __shfl_xor_sync(0xffffffffu, s1, o);
            s2 += __shfl_xor_sync(0xffffffffu, s2, o);
            s3 += __shfl_xor_sync(0xffffffffu, s3, o);
        }
        if (s0 > best[0]) { best[0] = s0; bl[0] = l; }
        if (s1 > best[1]) { best[1] = s1; bl[1] = l; }
        if (s2 > best[2]) { best[2] = s2; bl[2] = l; }
        if (s3 > best[3]) { best[3] = s3; bl[3] = l; }
    }
    if (lane == 0) {
#pragma unroll
        for (int i = 0; i < 4; i++) g_labels[b * T + tb + i] = bl[i];
    }
}

// ---------------------------------------------------------------------------
// K3: mean4[b,s,:] = mean of 4 vis rows;  maj4[b,s] = majority label of 4
// consecutive clip_labels (tie -> smallest label  ==  argmax-first over counts).
// grid (NS, B), 256 threads (thread = c).
// ---------------------------------------------------------------------------
__global__ void k_pool(const float* __restrict__ vis) {
    const int b = blockIdx.y, s = blockIdx.x, c = threadIdx.x;
    const size_t base = ((size_t)(b * T + s)) * C + c;
    float m = 0.25f * (vis[base] + vis[base + C] + vis[base + 2 * C] + vis[base + 3 * C]);
    g_mean4[((size_t)b * NS + s) * C + c] = m;

    if (c == 0) {
        int la[4];
#pragma unroll
        for (int i = 0; i < 4; i++) la[i] = g_labels[b * T + s + i];
        int bc = 0, blab = L;
#pragma unroll
        for (int i = 0; i < 4; i++) {
            int cnt = (la[0] == la[i]) + (la[1] == la[i]) +
                      (la[2] == la[i]) + (la[3] == la[i]);
            if (cnt > bc || (cnt == bc && la[i] < blab)) { bc = cnt; blab = la[i]; }
        }
        g_maj4[b * NS + s] = blab;
    }
}

// ---------------------------------------------------------------------------
// K4: out[b,w,k,c] = enc2[b, maj4[b,w+4k], c] * mean4[b, w+4k, c]
// grid (ceil(NW/32), B), 256 threads, dynamic smem:
//   enc2[b] (32KB) + 60-row mean4 tile (60KB) + 60 maj4 ints. Warp = fixed k,
//   loops 32 local w; 2x float4 per lane -> coalesced 1KB-row STG.128.
// ---------------------------------------------------------------------------
#define WT 32
__global__ void k_out(float* __restrict__ out) {
    extern __shared__ float sm[];
    float* enc2_s = sm;                       // 8192 floats
    float* mean_s = sm + L * C;               // 60*256 floats
    int*   maj_s  = (int*)(sm + L * C + 60 * C);

    const int b  = blockIdx.y;
    const int w0 = blockIdx.x * WT;

    for (int i = threadIdx.x; i < L * C; i += 256)
        enc2_s[i] = g_enc2[b * L * C + i];
    for (int i = threadIdx.x; i < 60 * C; i += 256) {
        int r = i >> 8, s = w0 + r;
        mean_s[i] = (s < NS) ? g_mean4[((size_t)b * NS + s) * C + (i & 255)] : 0.f;
    }
    if (threadIdx.x < 60) {
        int s = w0 + threadIdx.x;
        maj_s[threadIdx.x] = (s < NS) ? g_maj4[b * NS + s] : 0;
    }
    __syncthreads();

    const int k = threadIdx.x >> 5;          // warp id = chunk index
    const int lane = threadIdx.x & 31;

    for (int wl = 0; wl < WT; wl++) {
        const int w = w0 + wl;
        if (w >= NW) break;
        const int sl  = wl + 4 * k;
        const int lbl = maj_s[sl];
        const float4* mr = (const float4*)(mean_s + sl * C);
        const float4* er = (const float4*)(enc2_s + lbl * C);
        float4* orow = (float4*)(out + (((size_t)(b * NW + w)) * NCH + k) * C);

        float4 m0 = mr[lane],      e0 = er[lane];
        float4 m1 = mr[lane + 32], e1 = er[lane + 32];
        float4 o0 = make_float4(m0.x * e0.x, m0.y * e0.y, m0.z * e0.z, m0.w * e0.w);
        float4 o1 = make_float4(m1.x * e1.x, m1.y * e1.y, m1.z * e1.z, m1.w * e1.w);
        orow[lane]      = o0;
        orow[lane + 32] = o1;
    }
}

// ---------------------------------------------------------------------------
extern "C" void kernel_launch(void* const* d_in, const int* in_sizes, int n_in,
                              void* d_out, int out_size) {
    const float* vis   = (const float*)d_in[0];  // (B,T,C)
    const float* query = (const float*)d_in[1];  // (B,L,DQ)
    const float* W1    = (const float*)d_in[2];  // (DQ,C)
    const float* b1    = (const float*)d_in[3];  // (C,)
    const float* W2    = (const float*)d_in[4];  // (DQ,C)
    const float* b2    = (const float*)d_in[5];  // (C,)
    float* out = (float*)d_out;

    (void)in_sizes; (void)n_in; (void)out_size;

    k_enc_partial<<<dim3(DSPLIT, B), 256>>>(query, W1, W2);
    k_enc_reduce<<<B * L, 256>>>(b1, b2);
    k_labels<<<dim3(T / 32, B), 256>>>(vis);
    k_pool<<<dim3(NS, B), 256>>>(vis);

    const int smem_k4 = (L * C + 60 * C + 64) * sizeof(float);  // ~94.5 KB
    cudaFuncSetAttribute(k_out, cudaFuncAttributeMaxDynamicSharedMemorySize, smem_k4);
    k_out<<<dim3((NW + WT - 1) / WT, B), 256, smem_k4>>>(out);
}

// round 5
// speedup vs baseline: 1.2154x; 1.2154x over previous
#include <cuda_runtime.h>
#include <cstdint>

// Problem constants
#define B   8
#define T   2048
#define C   256
#define L   32
#define DQ  512
#define WSZ 32
#define NCH 8
#define CIC 4
#define NW  2017      // T - WSZ + 1
#define NS  2045      // T - CIC + 1 (distinct 4-window starts)
#define DSPLIT 16     // d-split for enc partial GEMM

// ---------------- scratch (device globals; no allocs allowed) ----------------
__device__ float g_part1[DSPLIT * B * L * C];   // 4 MB
__device__ float g_part2[DSPLIT * B * L * C];   // 4 MB
__device__ float g_enc1[B * L * C];             // 256 KB
__device__ float g_enc2[B * L * C];             // 256 KB
__device__ int   g_labels[B * T];               // 64 KB

// ---------------------------------------------------------------------------
// K1a: partial enc GEMMs.  enc{1,2}[b,l,c] = sum_d query[b,l,d]*W{1,2}[d,c]
// grid (DSPLIT, B), 256 threads.
// ---------------------------------------------------------------------------
__global__ void k_enc_partial(const float* __restrict__ query,
                              const float* __restrict__ W1,
                              const float* __restrict__ W2) {
    __shared__ float q_s[L * 32];   // [l][dd]
    const int b  = blockIdx.y;
    const int dc = blockIdx.x;
    const int d0 = dc * 32;

    for (int i = threadIdx.x; i < L * 32; i += 256) {
        int l = i >> 5, dd = i & 31;
        q_s[i] = query[((b * L + l) * DQ) + d0 + dd];
    }
    __syncthreads();

    const int warp = threadIdx.x >> 5, lane = threadIdx.x & 31;

    float4 a1[4][2], a2[4][2];
#pragma unroll
    for (int i = 0; i < 4; i++)
#pragma unroll
        for (int p = 0; p < 2; p++) {
            a1[i][p] = make_float4(0.f, 0.f, 0.f, 0.f);
            a2[i][p] = make_float4(0.f, 0.f, 0.f, 0.f);
        }

    for (int dd = 0; dd < 32; dd++) {
        const int d = d0 + dd;
        const float4* w1r = (const float4*)(W1 + d * C);
        const float4* w2r = (const float4*)(W2 + d * C);
        float4 w1a = w1r[lane], w1b = w1r[lane + 32];
        float4 w2a = w2r[lane], w2b = w2r[lane + 32];
#pragma unroll
        for (int i = 0; i < 4; i++) {
            float q = q_s[(warp * 4 + i) * 32 + dd];
            a1[i][0].x += q * w1a.x; a1[i][0].y += q * w1a.y;
            a1[i][0].z += q * w1a.z; a1[i][0].w += q * w1a.w;
            a1[i][1].x += q * w1b.x; a1[i][1].y += q * w1b.y;
            a1[i][1].z += q * w1b.z; a1[i][1].w += q * w1b.w;
            a2[i][0].x += q * w2a.x; a2[i][0].y += q * w2a.y;
            a2[i][0].z += q * w2a.z; a2[i][0].w += q * w2a.w;
            a2[i][1].x += q * w2b.x; a2[i][1].y += q * w2b.y;
            a2[i][1].z += q * w2b.z; a2[i][1].w += q * w2b.w;
        }
    }

#pragma unroll
    for (int i = 0; i < 4; i++) {
        int l = warp * 4 + i;
        float4* p1 = (float4*)(g_part1 + (((size_t)dc * B + b) * L + l) * C);
        float4* p2 = (float4*)(g_part2 + (((size_t)dc * B + b) * L + l) * C);
        p1[lane] = a1[i][0]; p1[lane + 32] = a1[i][1];
        p2[lane] = a2[i][0]; p2[lane + 32] = a2[i][1];
    }
}

// K1b: reduce d-split partials + bias. grid (B*L), 256 threads (thread = c).
__global__ void k_enc_reduce(const float* __restrict__ b1,
                             const float* __restrict__ b2) {
    const int b = blockIdx.x >> 5, l = blockIdx.x & 31, c = threadIdx.x;
    float s1 = 0.f, s2 = 0.f;
#pragma unroll
    for (int dc = 0; dc < DSPLIT; dc++) {
        size_t idx = (((size_t)dc * B + b) * L + l) * C + c;
        s1 += g_part1[idx];
        s2 += g_part2[idx];
    }
    g_enc1[(b * L + l) * C + c] = s1 + b1[c];
    g_enc2[(b * L + l) * C + c] = s2 + b2[c];
}

// ---------------------------------------------------------------------------
// K2: clip_labels[b,t] = argmax_l sum_c vis[b,t,c]*enc1[b,l,c]
// grid (T/32, B), 256 threads.
// ---------------------------------------------------------------------------
__global__ void k_labels(const float* __restrict__ vis) {
    __shared__ float e_s[L * C];   // 32 KB
    const int b = blockIdx.y, t0 = blockIdx.x * 32;

    for (int i = threadIdx.x; i < L * C; i += 256)
        e_s[i] = g_enc1[b * L * C + i];
    __syncthreads();

    const int warp = threadIdx.x >> 5, lane = threadIdx.x & 31;
    const int tb = t0 + warp * 4;

    float v[4][8];
#pragma unroll
    for (int i = 0; i < 4; i++) {
        const float* vr = vis + ((size_t)(b * T + tb + i)) * C;
#pragma unroll
        for (int j = 0; j < 8; j++) v[i][j] = vr[lane + 32 * j];
    }

    float best[4]; int bl[4];
#pragma unroll
    for (int i = 0; i < 4; i++) { best[i] = -3.4e38f; bl[i] = 0; }

    for (int l = 0; l < L; l++) {
        float s0 = 0.f, s1 = 0.f, s2 = 0.f, s3 = 0.f;
#pragma unroll
        for (int j = 0; j < 8; j++) {
            float e = e_s[l * C + lane + 32 * j];
            s0 += v[0][j] * e;
            s1 += v[1][j] * e;
            s2 += v[2][j] * e;
            s3 += v[3][j] * e;
        }
#pragma unroll
        for (int o = 16; o; o >>= 1) {
            s0 += __shfl_xor_sync(0xffffffffu, s0, o);
            s1 += __shfl_xor_sync(0xffffffffu, s1, o);
            s2 += __shfl_xor_sync(0xffffffffu, s2, o);
            s3 += __shfl_xor_sync(0xffffffffu, s3, o);
        }
        if (s0 > best[0]) { best[0] = s0; bl[0] = l; }
        if (s1 > best[1]) { best[1] = s1; bl[1] = l; }
        if (s2 > best[2]) { best[2] = s2; bl[2] = l; }
        if (s3 > best[3]) { best[3] = s3; bl[3] = l; }
    }
    if (lane == 0) {
#pragma unroll
        for (int i = 0; i < 4; i++) g_labels[b * T + tb + i] = bl[i];
    }
}

// ---------------------------------------------------------------------------
// K4 (fused): out[b,w,k,c] = enc2[b, maj4(b,w+4k), c] * mean4(b,w+4k,c)
// mean4 computed in-block from a 64-row vis smem tile with a SLIDING running
// sum (2 row-reads/iter instead of 4); maj4 computed in-block from g_labels.
// No g_mean4 scratch, no k_pool kernel.
// Smem: enc2[b] 32KB + vis tile 64KB + labels/maj ~0.5KB  (~96.5KB, 2 blk/SM)
// grid (ceil(NW/32), B), 256 threads; warp = chunk k.
// ---------------------------------------------------------------------------
#define WT 32
__global__ void k_out(const float* __restrict__ vis, float* __restrict__ out) {
    extern __shared__ float sm[];
    float* enc2_s = sm;                        // 8192 floats
    float* vis_s  = sm + L * C;                // 64*256 floats
    int*   lab_s  = (int*)(sm + L * C + 64 * C);   // 64 ints
    int*   maj_s  = lab_s + 64;                    // 60 ints

    const int b  = blockIdx.y;
    const int w0 = blockIdx.x * WT;

    for (int i = threadIdx.x; i < L * C; i += 256)
        enc2_s[i] = g_enc2[b * L * C + i];
    {
        // vis rows t in [w0, w0+64) ; last block (w0=2016) stops at T.
        const int nrow = (T - w0 < 64) ? (T - w0) : 64;
        const float4* src = (const float4*)(vis + ((size_t)(b * T + w0)) * C);
        float4* dst = (float4*)vis_s;
        for (int i = threadIdx.x; i < nrow * 64; i += 256)
            dst[i] = src[i];
    }
    if (threadIdx.x < 64) {
        int t = w0 + threadIdx.x;
        lab_s[threadIdx.x] = (t < T) ? g_labels[b * T + t] : 0;
    }
    __syncthreads();

    if (threadIdx.x < 60) {
        int la[4];
#pragma unroll
        for (int i = 0; i < 4; i++) la[i] = lab_s[threadIdx.x + i];
        int bc = 0, blab = L;
#pragma unroll
        for (int i = 0; i < 4; i++) {
            int cnt = (la[0] == la[i]) + (la[1] == la[i]) +
                      (la[2] == la[i]) + (la[3] == la[i]);
            if (cnt > bc || (cnt == bc && la[i] < blab)) { bc = cnt; blab = la[i]; }
        }
        maj_s[threadIdx.x] = blab;
    }
    __syncthreads();

    const int k    = threadIdx.x >> 5;         // warp id = chunk index
    const int lane = threadIdx.x & 31;

    // Running sum of 4 vis rows for s = w0 + 4k (local rows 4k..4k+3)
    float4 s0 = make_float4(0.f, 0.f, 0.f, 0.f);
    float4 s1 = make_float4(0.f, 0.f, 0.f, 0.f);
#pragma unroll
    for (int r = 0; r < 4; r++) {
        const float4* vr = (const float4*)(vis_s + (4 * k + r) * C);
        float4 a = vr[lane], bb = vr[lane + 32];
        s0.x += a.x;  s0.y += a.y;  s0.z += a.z;  s0.w += a.w;
        s1.x += bb.x; s1.y += bb.y; s1.z += bb.z; s1.w += bb.w;
    }

    for (int wl = 0; wl < WT; wl++) {
        const int w = w0 + wl;
        if (w >= NW) break;
        const int sl  = wl + 4 * k;            // local s index
        const int lbl = maj_s[sl];
        const float4* er = (const float4*)(enc2_s + lbl * C);
        float4 e0 = er[lane], e1 = er[lane + 32];

        float4* orow = (float4*)(out + (((size_t)(b * NW + w)) * NCH + k) * C);
        orow[lane] = make_float4(0.25f * s0.x * e0.x, 0.25f * s0.y * e0.y,
                                 0.25f * s0.z * e0.z, 0.25f * s0.w * e0.w);
        orow[lane + 32] = make_float4(0.25f * s1.x * e1.x, 0.25f * s1.y * e1.y,
                                      0.25f * s1.z * e1.z, 0.25f * s1.w * e1.w);

        if (wl < WT - 1 && w + 1 < NW) {
            const float4* va = (const float4*)(vis_s + (sl + 4) * C);  // enters
            const float4* vb = (const float4*)(vis_s + sl * C);        // leaves
            float4 a0 = va[lane], a1 = va[lane + 32];
            float4 b0 = vb[lane], b1 = vb[lane + 32];
            s0.x += a0.x - b0.x; s0.y += a0.y - b0.y;
            s0.z += a0.z - b0.z; s0.w += a0.w - b0.w;
            s1.x += a1.x - b1.x; s1.y += a1.y - b1.y;
            s1.z += a1.z - b1.z; s1.w += a1.w - b1.w;
        }
    }
}

// ---------------------------------------------------------------------------
extern "C" void kernel_launch(void* const* d_in, const int* in_sizes, int n_in,
                              void* d_out, int out_size) {
    const float* vis   = (const float*)d_in[0];  // (B,T,C)
    const float* query = (const float*)d_in[1];  // (B,L,DQ)
    const float* W1    = (const float*)d_in[2];  // (DQ,C)
    const float* b1    = (const float*)d_in[3];  // (C,)
    const float* W2    = (const float*)d_in[4];  // (DQ,C)
    const float* b2    = (const float*)d_in[5];  // (C,)
    float* out = (float*)d_out;

    (void)in_sizes; (void)n_in; (void)out_size;

    k_enc_partial<<<dim3(DSPLIT, B), 256>>>(query, W1, W2);
    k_enc_reduce<<<B * L, 256>>>(b1, b2);
    k_labels<<<dim3(T / 32, B), 256>>>(vis);

    const int smem_k4 = (L * C + 64 * C) * sizeof(float) + 128 * sizeof(int);
    cudaFuncSetAttribute(k_out, cudaFuncAttributeMaxDynamicSharedMemorySize, smem_k4);
    k_out<<<dim3((NW + WT - 1) / WT, B), 256, smem_k4>>>(vis, out);
}